// round 2
// baseline (speedup 1.0000x reference)
#include <cuda_runtime.h>

// Problem geometry (fixed by the dataset)
#define W     1920
#define H     1080
#define NPL   6            // B*C planes
#define HWSZ  (H*W)
#define NTOT  (NPL*HWSZ)   // 12,441,600
#define KS    51
#define RAD   25

// Scratch (allocation-free rule: __device__ globals)
__device__ float g_tmpA[NTOT];
__device__ float g_tmpB[NTOT];
__device__ float g_tmpC[NTOT];
__device__ float g_k1[KS];

// --- 1D kernel extraction: the 2D kernel is an outer product k1*k1^T with
// sum(k1)=1, so row-sums recover k1 exactly (up to fp32 rounding). ---
__global__ void k1d_kernel(const float* __restrict__ k2d) {
    int i = threadIdx.x;
    if (i < KS) {
        float s = 0.f;
        #pragma unroll
        for (int j = 0; j < KS; j++) s += k2d[i * KS + j];
        g_k1[i] = s;
    }
}

__device__ __forceinline__ int reflect_idx(int i, int n) {
    // jnp.pad mode='reflect' (mirror WITHOUT repeating the edge)
    if (i < 0)  i = -i;
    if (i >= n) i = 2 * n - 2 - i;
    return i;
}

// ---------------- Horizontal 51-tap conv, reflect pad ----------------
#define HBX 256
__global__ void hconv_kernel(const float* __restrict__ in, float* __restrict__ out) {
    __shared__ float s[HBX + 2 * RAD];
    __shared__ float sk[KS];
    const int tid = threadIdx.x;
    const int row = blockIdx.y;           // 0 .. NPL*H-1
    const int x0  = blockIdx.x * HBX;
    const float* rin = in + (long)row * W;

    if (tid < KS) sk[tid] = g_k1[tid];
    for (int i = tid; i < HBX + 2 * RAD; i += HBX) {
        int x = reflect_idx(x0 - RAD + i, W);
        s[i] = rin[x];
    }
    __syncthreads();

    int x = x0 + tid;
    if (x < W) {
        float sum = 0.f;
        #pragma unroll
        for (int t = 0; t < KS; t++) sum = fmaf(s[tid + t], sk[t], sum);
        out[(long)row * W + x] = sum;
    }
}

// ---------------- Vertical conv tiles: 32 wide x 64 tall outputs ------------
#define VBX 32
#define VBY 8
#define VRY 8
#define VTH (VBY * VRY)   // 64 output rows per block

// Pass 3: blur = Vconv(tmpA); residual/mask fused. blur -> blur_out (d_out),
// mask -> mask_out (tmpB).
__global__ void vconv_mask_kernel(const float* __restrict__ in,
                                  const float* __restrict__ img,
                                  float* __restrict__ blur_out,
                                  float* __restrict__ mask_out) {
    __shared__ float s[VTH + 2 * RAD][VBX];
    __shared__ float sk[KS];
    const int tx = threadIdx.x, ty = threadIdx.y;
    const int tid = ty * VBX + tx;
    const int x  = blockIdx.x * VBX + tx;          // W % 32 == 0, no guard
    const int y0 = blockIdx.y * VTH;
    const long pbase = (long)blockIdx.z * HWSZ;

    if (tid < KS) sk[tid] = g_k1[tid];
    for (int i = ty; i < VTH + 2 * RAD; i += VBY) {
        int y = reflect_idx(y0 - RAD + i, H);
        s[i][tx] = in[pbase + (long)y * W + x];
    }
    __syncthreads();

    #pragma unroll
    for (int r = 0; r < VRY; r++) {
        int yl = ty * VRY + r;
        int y  = y0 + yl;
        if (y < H) {
            float sum = 0.f;
            #pragma unroll
            for (int t = 0; t < KS; t++) sum = fmaf(s[yl + t][tx], sk[t], sum);
            long idx = pbase + (long)y * W + x;
            float im  = img[idx];
            float res = im - sum;
            blur_out[idx] = sum;
            mask_out[idx] = (fabsf(res) * 255.0f > 10.0f) ? 1.0f : 0.0f;
        }
    }
}

// Pass 5: soft_mask = Vconv(tmpC); final blend fused. blur is read from the
// same buffer we write (d_out) at the SAME index per thread -> no restrict.
__global__ void vconv_final_kernel(const float* __restrict__ in,
                                   const float* __restrict__ img,
                                   float* blur_and_out) {
    __shared__ float s[VTH + 2 * RAD][VBX];
    __shared__ float sk[KS];
    const int tx = threadIdx.x, ty = threadIdx.y;
    const int tid = ty * VBX + tx;
    const int x  = blockIdx.x * VBX + tx;
    const int y0 = blockIdx.y * VTH;
    const long pbase = (long)blockIdx.z * HWSZ;

    if (tid < KS) sk[tid] = g_k1[tid];
    for (int i = ty; i < VTH + 2 * RAD; i += VBY) {
        int y = reflect_idx(y0 - RAD + i, H);
        s[i][tx] = in[pbase + (long)y * W + x];
    }
    __syncthreads();

    #pragma unroll
    for (int r = 0; r < VRY; r++) {
        int yl = ty * VRY + r;
        int y  = y0 + yl;
        if (y < H) {
            float soft = 0.f;
            #pragma unroll
            for (int t = 0; t < KS; t++) soft = fmaf(s[yl + t][tx], sk[t], soft);
            long idx = pbase + (long)y * W + x;
            float im  = img[idx];
            float bl  = blur_and_out[idx];
            float res = im - bl;
            float sharp = fminf(fmaxf(fmaf(0.5f, res, im), 0.0f), 1.0f);
            blur_and_out[idx] = soft * sharp + (1.0f - soft) * im;
        }
    }
}

extern "C" void kernel_launch(void* const* d_in, const int* in_sizes, int n_in,
                              void* d_out, int out_size) {
    const float* img = (const float*)d_in[0];   // [2,3,1080,1920] fp32
    const float* k2d = (const float*)d_in[1];   // [51,51] fp32
    float* out = (float*)d_out;

    float *tmpA, *tmpB, *tmpC;
    cudaGetSymbolAddress((void**)&tmpA, g_tmpA);
    cudaGetSymbolAddress((void**)&tmpB, g_tmpB);
    cudaGetSymbolAddress((void**)&tmpC, g_tmpC);

    // 1) recover 1D kernel
    k1d_kernel<<<1, 64>>>(k2d);

    dim3 hgrid((W + HBX - 1) / HBX, NPL * H);
    dim3 vgrid(W / VBX, (H + VTH - 1) / VTH, NPL);
    dim3 vblk(VBX, VBY);

    // 2) horizontal blur of img
    hconv_kernel<<<hgrid, HBX>>>(img, tmpA);
    // 3) vertical blur -> blur (stored in d_out) + mask (tmpB)
    vconv_mask_kernel<<<vgrid, vblk>>>(tmpA, img, out, tmpB);
    // 4) horizontal blur of mask
    hconv_kernel<<<hgrid, HBX>>>(tmpB, tmpC);
    // 5) vertical blur of mask + final blend -> d_out
    vconv_final_kernel<<<vgrid, vblk>>>(tmpC, img, out);
}